// round 7
// baseline (speedup 1.0000x reference)
#include <cuda_runtime.h>
#include <cuda_bf16.h>

#define B_ROWS 16384
#define NCLASS 1000
#define DIM 1024
#define WARPS_PER_BLOCK 8
#define THREADS (WARPS_PER_BLOCK * 32)
#define NBLOCKS (B_ROWS / WARPS_PER_BLOCK)   // 2048

__device__ float g_partials[NBLOCKS];
__device__ unsigned int g_count;   // zero at load; reset each run -> graph-replay safe

// One warp per row. __launch_bounds__(256,2) gives ptxas a 128-reg budget so the
// 16 front-batched LDG.128s can actually stay in flight (MLP=16/thread).
__global__ __launch_bounds__(THREADS, 2) void proximity_fused_kernel(
    const float* __restrict__ x,
    const int* __restrict__ labels,
    const float* __restrict__ centers,
    float* __restrict__ out)
{
    const int warp = threadIdx.x >> 5;
    const int lane = threadIdx.x & 31;
    const int row  = blockIdx.x * WARPS_PER_BLOCK + warp;

    // Dependent-chain head: label load first.
    int lab = labels[row];

    const float4* __restrict__ xr =
        reinterpret_cast<const float4*>(x + (size_t)row * DIM);

    // Front-batch all 8 x loads (independent of lab).
    float4 xv0 = xr[lane +   0];
    float4 xv1 = xr[lane +  32];
    float4 xv2 = xr[lane +  64];
    float4 xv3 = xr[lane +  96];
    float4 xv4 = xr[lane + 128];
    float4 xv5 = xr[lane + 160];
    float4 xv6 = xr[lane + 192];
    float4 xv7 = xr[lane + 224];

    lab = min(max(lab, 0), NCLASS - 1);   // defensive clamp
    const float4* __restrict__ cr =
        reinterpret_cast<const float4*>(centers + (size_t)lab * DIM);

    // Front-batch all 8 center loads (L2-resident gather).
    float4 cv0 = cr[lane +   0];
    float4 cv1 = cr[lane +  32];
    float4 cv2 = cr[lane +  64];
    float4 cv3 = cr[lane +  96];
    float4 cv4 = cr[lane + 128];
    float4 cv5 = cr[lane + 160];
    float4 cv6 = cr[lane + 192];
    float4 cv7 = cr[lane + 224];

    float sxx = 0.f, scc = 0.f, sxc = 0.f;
    #define ACC(xv, cv)                         \
        sxx = fmaf(xv.x, xv.x, sxx);            \
        sxx = fmaf(xv.y, xv.y, sxx);            \
        sxx = fmaf(xv.z, xv.z, sxx);            \
        sxx = fmaf(xv.w, xv.w, sxx);            \
        scc = fmaf(cv.x, cv.x, scc);            \
        scc = fmaf(cv.y, cv.y, scc);            \
        scc = fmaf(cv.z, cv.z, scc);            \
        scc = fmaf(cv.w, cv.w, scc);            \
        sxc = fmaf(xv.x, cv.x, sxc);            \
        sxc = fmaf(xv.y, cv.y, sxc);            \
        sxc = fmaf(xv.z, cv.z, sxc);            \
        sxc = fmaf(xv.w, cv.w, sxc);

    ACC(xv0, cv0) ACC(xv1, cv1) ACC(xv2, cv2) ACC(xv3, cv3)
    ACC(xv4, cv4) ACC(xv5, cv5) ACC(xv6, cv6) ACC(xv7, cv7)
    #undef ACC

    #pragma unroll
    for (int off = 16; off > 0; off >>= 1) {
        sxx += __shfl_down_sync(0xFFFFFFFFu, sxx, off);
        scc += __shfl_down_sync(0xFFFFFFFFu, scc, off);
        sxc += __shfl_down_sync(0xFFFFFFFFu, sxc, off);
    }

    __shared__ float s_dist[WARPS_PER_BLOCK];
    if (lane == 0) {
        const float eps = 1e-12f;
        float nx = fmaxf(sqrtf(sxx), eps);
        float nc = fmaxf(sqrtf(scc), eps);
        float d = sxx / (nx * nx) + scc / (nc * nc) - 2.0f * sxc / (nx * nc);
        d = fminf(fmaxf(d, 1e-12f), 1e12f);
        s_dist[warp] = d;
    }
    __syncthreads();

    __shared__ bool s_last;
    if (threadIdx.x == 0) {
        float s = 0.f;
        #pragma unroll
        for (int w = 0; w < WARPS_PER_BLOCK; ++w) s += s_dist[w];
        g_partials[blockIdx.x] = s;
        __threadfence();
        unsigned int ticket = atomicAdd(&g_count, 1u);
        s_last = (ticket == NBLOCKS - 1);
    }
    __syncthreads();

    if (s_last) {
        // Deterministic final reduction over 2048 partials (L2-resident).
        __shared__ float sm[THREADS];
        float s = 0.f;
        #pragma unroll
        for (int i = threadIdx.x; i < NBLOCKS; i += THREADS) s += g_partials[i];
        sm[threadIdx.x] = s;
        __syncthreads();
        #pragma unroll
        for (int stride = THREADS / 2; stride > 0; stride >>= 1) {
            if (threadIdx.x < stride) sm[threadIdx.x] += sm[threadIdx.x + stride];
            __syncthreads();
        }
        if (threadIdx.x == 0) {
            out[0] = sm[0] * (1.0f / (float)B_ROWS);
            g_count = 0;
        }
    }
}

extern "C" void kernel_launch(void* const* d_in, const int* in_sizes, int n_in,
                              void* d_out, int out_size)
{
    const float* x       = (const float*)d_in[0];
    const int*   labels  = (const int*)d_in[1];
    const float* centers = (const float*)d_in[2];
    float*       out     = (float*)d_out;

    proximity_fused_kernel<<<NBLOCKS, THREADS>>>(x, labels, centers, out);
}